// round 2
// baseline (speedup 1.0000x reference)
#include <cuda_runtime.h>

#define N_AG 4096
#define M_CL 256
#define KD 32
#define SPLIT 8
#define CHUNK (N_AG / SPLIT)   /* 512 */
#define TILE 32
#define PSTRIDE 1064           /* 1024 S + 32 s + Z + cnt, padded (16B-mult) */
#define W_EPS 1e-6f

typedef unsigned long long u64;

// static scratch (no allocations allowed)
__device__ float g_v[N_AG * KD];
__device__ float g_part[M_CL * SPLIT * PSTRIDE];

__device__ __forceinline__ u64 pack2(float x) {
  u64 d;
  asm("mov.b64 %0, {%1, %1};" : "=l"(d) : "f"(x));
  return d;
}
__device__ __forceinline__ void ffma2(u64& d, u64 a, u64 b) {
  asm("fma.rn.f32x2 %0, %1, %2, %3;" : "=l"(d) : "l"(a), "l"(b), "l"(d));
}

// ---------------------------------------------------------------------------
// Kernel A: batched 32x32 SPD solve. TWO matrices per warp: lanes 0-15 hold
// matrix 2w (rows hl, hl+16), lanes 16-31 hold matrix 2w+1. Width-16 shfl
// broadcasts serve both matrices at once -> half the SHFL instructions of the
// one-matrix-per-warp version (SHFL was the measured bottleneck).
// ---------------------------------------------------------------------------
__global__ void __launch_bounds__(256) solve_kernel(const float* __restrict__ A,
                                                    const float* __restrict__ rhs) {
  int warp = (blockIdx.x * blockDim.x + threadIdx.x) >> 5;
  int lane = threadIdx.x & 31;
  int half = lane >> 4;
  int hl   = lane & 15;
  int mat  = warp * 2 + half;

  const float* Abase = A + (size_t)mat * (KD * KD);
  float a0[KD], a1[KD];
#pragma unroll
  for (int q = 0; q < KD / 4; q++) {
    float4 t4 = *reinterpret_cast<const float4*>(Abase + hl * KD + 4 * q);
    a0[4 * q + 0] = t4.x; a0[4 * q + 1] = t4.y;
    a0[4 * q + 2] = t4.z; a0[4 * q + 3] = t4.w;
    float4 u4 = *reinterpret_cast<const float4*>(Abase + (hl + 16) * KD + 4 * q);
    a1[4 * q + 0] = u4.x; a1[4 * q + 1] = u4.y;
    a1[4 * q + 2] = u4.z; a1[4 * q + 3] = u4.w;
  }
  float b0 = rhs[mat * KD + hl];
  float b1 = rhs[mat * KD + hl + 16];

#pragma unroll
  for (int j = 0; j < KD; j++) {
    float pv = (j < 16) ? a0[j] : a1[j];
    float pd = __shfl_sync(0xffffffffu, pv, j & 15, 16);
    float inv = 1.0f / pd;
    bool isp = (hl == (j & 15));
    if (j < 16) {
      if (isp) {
#pragma unroll
        for (int k = j + 1; k < KD; k++) a0[k] *= inv;
        b0 *= inv;
      }
    } else {
      if (isp) {
#pragma unroll
        for (int k = j + 1; k < KD; k++) a1[k] *= inv;
        b1 *= inv;
      }
    }
    float f0 = (j == hl)      ? 0.0f : a0[j];
    float f1 = (j == hl + 16) ? 0.0f : a1[j];
#pragma unroll
    for (int k = j + 1; k < KD; k++) {
      float cv = (j < 16) ? a0[k] : a1[k];
      float pk = __shfl_sync(0xffffffffu, cv, j & 15, 16);
      a0[k] = fmaf(-f0, pk, a0[k]);
      a1[k] = fmaf(-f1, pk, a1[k]);
    }
    float bv = (j < 16) ? b0 : b1;
    float pb = __shfl_sync(0xffffffffu, bv, j & 15, 16);
    b0 = fmaf(-f0, pb, b0);
    b1 = fmaf(-f1, pb, b1);
  }
  g_v[mat * KD + hl] = b0;
  g_v[mat * KD + hl + 16] = b1;
}

// ---------------------------------------------------------------------------
// Kernel B: weighted moments with packed f32x2 FMAs. grid = (32 m-groups,
// 8 n-chunks), 256 thr/block. Warp w handles m = mg*8+w over its 512-n chunk.
// Lane owns a 4(k) x 8(l) tile of S; the 8 l-values live as 4 b64 f32-pairs,
// so the per-n update is 16 FFMA2 instead of 32 FFMA on the fma pipe.
// ---------------------------------------------------------------------------
__global__ void __launch_bounds__(256) moments_kernel(const float* __restrict__ W) {
  __shared__ __align__(16) float vt[TILE * KD];  // [n][k]
  __shared__ float wt[TILE * 8];                 // [n][m_in_group]

  int t    = threadIdx.x;
  int wid  = t >> 5;
  int lane = t & 31;
  int mg   = blockIdx.x;   // 0..31
  int c    = blockIdx.y;   // 0..7
  int m    = mg * 8 + wid;

  int kq = lane >> 2, lq = lane & 3;
  int kb = 4 * kq, lb = 8 * lq;

  u64 acc2[4][4];
#pragma unroll
  for (int i = 0; i < 4; i++)
#pragma unroll
    for (int j = 0; j < 4; j++) acc2[i][j] = 0ull;
  float s_acc = 0.0f, Z = 0.0f, cnt = 0.0f;

  int n0 = c * CHUNK;
  int wn = t >> 3, wm = t & 7;  // w-tile loader coords (32n x 8m)

  // prefetch tile 0
  float4 vpre = *reinterpret_cast<const float4*>(&g_v[n0 * KD + 4 * t]);
  float  wpre = W[(size_t)(n0 + wn) * M_CL + mg * 8 + wm];

  const int NT = CHUNK / TILE;  // 16
  for (int nt = 0; nt < NT; nt++) {
    *reinterpret_cast<float4*>(&vt[4 * t]) = vpre;
    wt[wn * 8 + wm] = (wpre >= W_EPS) ? wpre : 0.0f;
    __syncthreads();
    if (nt + 1 < NT) {
      int nn = n0 + (nt + 1) * TILE;
      vpre = *reinterpret_cast<const float4*>(&g_v[nn * KD + 4 * t]);
      wpre = W[(size_t)(nn + wn) * M_CL + mg * 8 + wm];
    }
#pragma unroll 4
    for (int n = 0; n < TILE; n++) {
      float w = wt[n * 8 + wid];                 // broadcast
      const float* vr = &vt[n * KD];
      float4 vk = *reinterpret_cast<const float4*>(vr + kb);
      ulonglong2 p0 = *reinterpret_cast<const ulonglong2*>(vr + lb);
      ulonglong2 p1 = *reinterpret_cast<const ulonglong2*>(vr + lb + 4);
      float  sv = vr[lane];
      u64 vp0 = p0.x, vp1 = p0.y, vp2 = p1.x, vp3 = p1.y;
      u64 tp0 = pack2(w * vk.x);
      u64 tp1 = pack2(w * vk.y);
      u64 tp2 = pack2(w * vk.z);
      u64 tp3 = pack2(w * vk.w);
      ffma2(acc2[0][0], tp0, vp0); ffma2(acc2[0][1], tp0, vp1);
      ffma2(acc2[0][2], tp0, vp2); ffma2(acc2[0][3], tp0, vp3);
      ffma2(acc2[1][0], tp1, vp0); ffma2(acc2[1][1], tp1, vp1);
      ffma2(acc2[1][2], tp1, vp2); ffma2(acc2[1][3], tp1, vp3);
      ffma2(acc2[2][0], tp2, vp0); ffma2(acc2[2][1], tp2, vp1);
      ffma2(acc2[2][2], tp2, vp2); ffma2(acc2[2][3], tp2, vp3);
      ffma2(acc2[3][0], tp3, vp0); ffma2(acc2[3][1], tp3, vp1);
      ffma2(acc2[3][2], tp3, vp2); ffma2(acc2[3][3], tp3, vp3);
      s_acc = fmaf(w, sv, s_acc);
      Z += w;
      cnt += (w > 0.0f) ? 1.0f : 0.0f;
    }
    __syncthreads();
  }

  float* p = g_part + (size_t)(m * SPLIT + c) * PSTRIDE;
#pragma unroll
  for (int i = 0; i < 4; i++) {
    ulonglong2 o0 = make_ulonglong2(acc2[i][0], acc2[i][1]);
    ulonglong2 o1 = make_ulonglong2(acc2[i][2], acc2[i][3]);
    *reinterpret_cast<ulonglong2*>(p + (kb + i) * KD + lb)     = o0;
    *reinterpret_cast<ulonglong2*>(p + (kb + i) * KD + lb + 4) = o1;
  }
  p[1024 + lane] = s_acc;
  if (lane == 0) { p[1056] = Z; p[1057] = cnt; }
}

// ---------------------------------------------------------------------------
// Kernel C: per-m finalize. Reduce 8 chunk partials; G = Omega^2 on the fly;
// psi = tr(G S)/Z - ||Omega s||^2 / Z^2, zeroed when count < 2.
// ---------------------------------------------------------------------------
__global__ void __launch_bounds__(256) finalize_kernel(const float* __restrict__ Omega,
                                                       float* __restrict__ out) {
  __shared__ float sS[1024];
  __shared__ float sO[1024];
  __shared__ float ssv[KD];
  __shared__ float red[256];
  __shared__ float s_trGS, s_Z, s_cnt;

  int m = blockIdx.x, t = threadIdx.x;
  const float* pb = g_part + (size_t)m * SPLIT * PSTRIDE;

  for (int e = t; e < 1024; e += 256) {
    float a = 0.0f;
#pragma unroll
    for (int c2 = 0; c2 < SPLIT; c2++) a += pb[c2 * PSTRIDE + e];
    sS[e] = a;
  }
  if (t < KD) {
    float a = 0.0f;
#pragma unroll
    for (int c2 = 0; c2 < SPLIT; c2++) a += pb[c2 * PSTRIDE + 1024 + t];
    ssv[t] = a;
  }
  if (t == 0) {
    float z = 0.0f, cn = 0.0f;
#pragma unroll
    for (int c2 = 0; c2 < SPLIT; c2++) { z += pb[c2 * PSTRIDE + 1056]; cn += pb[c2 * PSTRIDE + 1057]; }
    s_Z = z; s_cnt = cn;
  }
  for (int e = t; e < 1024; e += 256) sO[e] = Omega[(size_t)m * 1024 + e];
  __syncthreads();

  float partial = 0.0f;
  for (int e = t; e < 1024; e += 256) {
    int k = e >> 5, l = e & 31;
    float g = 0.0f;
#pragma unroll
    for (int q = 0; q < KD; q++) g = fmaf(sO[k * KD + q], sO[q * KD + l], g);
    partial = fmaf(g, sS[e], partial);
  }
  red[t] = partial;
  __syncthreads();
  for (int s = 128; s > 0; s >>= 1) { if (t < s) red[t] += red[t + s]; __syncthreads(); }
  if (t == 0) s_trGS = red[0];
  __syncthreads();

  float up = 0.0f;
  if (t < KD) {
    float u = 0.0f;
#pragma unroll
    for (int q = 0; q < KD; q++) u = fmaf(sO[t * KD + q], ssv[q], u);
    up = u * u;
  }
  red[t] = up;
  __syncthreads();
  for (int s = 128; s > 0; s >>= 1) { if (t < s) red[t] += red[t + s]; __syncthreads(); }

  if (t == 0) {
    float Z   = fmaxf(s_Z, 1e-30f);
    float psi = s_trGS / Z - red[0] / (Z * Z);
    out[m] = (s_cnt >= 1.5f) ? psi : 0.0f;
  }
}

// ---------------------------------------------------------------------------
extern "C" void kernel_launch(void* const* d_in, const int* in_sizes, int n_in,
                              void* d_out, int out_size) {
  const float* W            = (const float*)d_in[0];  // (N, M)
  const float* mu_s         = (const float*)d_in[1];  // (N, K)
  const float* omega_child  = (const float*)d_in[2];  // (N, K, K)
  const float* omega_parent = (const float*)d_in[3];  // (M, K, K)
  float* out = (float*)d_out;                         // (M,)

  solve_kernel<<<N_AG / 16, 256>>>(omega_child, mu_s);  // 2 matrices per warp
  dim3 gB(M_CL / 8, SPLIT);
  moments_kernel<<<gB, 256>>>(W);
  finalize_kernel<<<M_CL, 256>>>(omega_parent, out);
}

// round 3
// speedup vs baseline: 3.5509x; 3.5509x over previous
#include <cuda_runtime.h>

#define N_AG 4096
#define M_CL 256
#define KD 32
#define NF 561            /* 32 v + 528 sym-pairs + 1 ones */
#define FPAD 576          /* padded feature stride */
#define KSPLIT 16
#define KCH (N_AG / KSPLIT)   /* 256 */
#define W_EPS 1e-6f

// static scratch (no allocations allowed)
__device__ float g_v[N_AG * KD];
__device__ float g_P[(size_t)N_AG * FPAD];          // features, pad cols stay 0
__device__ float g_part[(size_t)KSPLIT * M_CL * FPAD];
__device__ float g_cnt[32 * M_CL];

// decode flat triangular index t in [0,528) -> (k,l), k<=l
__device__ __forceinline__ void tri_decode(int t, int& k, int& l) {
  int kk = (int)((65.0f - sqrtf(4225.0f - 8.0f * (float)t)) * 0.5f);
  if (kk < 0) kk = 0;
  if (kk > 31) kk = 31;
  while (kk > 0 && (kk * 32 - kk * (kk - 1) / 2) > t) kk--;
  while (((kk + 1) * 32 - (kk + 1) * kk / 2) <= t) kk++;
  k = kk;
  l = kk + (t - (kk * 32 - kk * (kk - 1) / 2));
}

// ---------------------------------------------------------------------------
// Kernel A (reverted to R1): batched 32x32 SPD solve, one warp per matrix,
// register Gauss-Jordan; pivot rows broadcast via shfl.
// ---------------------------------------------------------------------------
__global__ void __launch_bounds__(256) solve_kernel(const float* __restrict__ A,
                                                    const float* __restrict__ rhs) {
  int gw   = (blockIdx.x * blockDim.x + threadIdx.x) >> 5;
  int lane = threadIdx.x & 31;
  const float* Ar = A + (size_t)gw * (KD * KD) + lane * KD;

  float a[KD];
#pragma unroll
  for (int q = 0; q < KD / 4; q++) {
    float4 t4 = *reinterpret_cast<const float4*>(Ar + 4 * q);
    a[4 * q + 0] = t4.x; a[4 * q + 1] = t4.y;
    a[4 * q + 2] = t4.z; a[4 * q + 3] = t4.w;
  }
  float b = rhs[gw * KD + lane];

#pragma unroll
  for (int j = 0; j < KD; j++) {
    float pd  = __shfl_sync(0xffffffffu, a[j], j);
    float inv = 1.0f / pd;
    if (lane == j) {
#pragma unroll
      for (int k = j + 1; k < KD; k++) a[k] *= inv;
      b *= inv;
    }
    float f = (lane == j) ? 0.0f : a[j];
#pragma unroll
    for (int k = j + 1; k < KD; k++) {
      float pk = __shfl_sync(0xffffffffu, a[k], j);
      a[k] = fmaf(-f, pk, a[k]);
    }
    float pb = __shfl_sync(0xffffffffu, b, j);
    b = fmaf(-f, pb, b);
  }
  g_v[gw * KD + lane] = b;  // v, row-major [n][k]
}

// ---------------------------------------------------------------------------
// Kernel B1: build feature matrix P[n] = [v_0..v_31, {v_k v_l}_{k<=l}, 1].
// One warp per n; lane strides the 561 features.
// ---------------------------------------------------------------------------
__global__ void __launch_bounds__(256) buildP_kernel() {
  __shared__ float sv[8][KD];
  int t = threadIdx.x, wid = t >> 5, lane = t & 31;
  int n = blockIdx.x * 8 + wid;

  sv[wid][lane] = g_v[n * KD + lane];
  __syncwarp();

  float* Pn = g_P + (size_t)n * FPAD;
  const float* v = sv[wid];
  for (int f = lane; f < NF; f += 32) {
    float val;
    if (f < 32) {
      val = v[f];
    } else if (f < 560) {
      int k, l;
      tri_decode(f - 32, k, l);
      val = v[k] * v[l];
    } else {
      val = 1.0f;
    }
    Pn[f] = val;
  }
}

// ---------------------------------------------------------------------------
// Kernel B2: mask count per m.  cnt_part[blk][m] = #{n in chunk : W[n][m] >= eps}
// ---------------------------------------------------------------------------
__global__ void __launch_bounds__(256) cnt_kernel(const float* __restrict__ W) {
  int m = threadIdx.x;
  int nb = blockIdx.x * 128;
  float c = 0.0f;
  for (int r = 0; r < 128; r++)
    c += (W[(size_t)(nb + r) * M_CL + m] >= W_EPS) ? 1.0f : 0.0f;
  g_cnt[blockIdx.x * M_CL + m] = c;
}

// ---------------------------------------------------------------------------
// Kernel C: GEMM  D[m, f] = sum_n wmask[n, m] * P[n, f].
// grid (9 f-tiles x 2 m-tiles x 16 k-splits), 256 thr.
// Block tile 128m x 64f, K-chunk 32; thread tile 8m x 4f.
// Per k: 3x LDS.128 + 32 FFMA  ->  fma-pipe bound.
// ---------------------------------------------------------------------------
__global__ void __launch_bounds__(256) gemm_kernel(const float* __restrict__ W) {
  __shared__ __align__(16) float sA[32 * 128];  // [k][m] (masked w)
  __shared__ __align__(16) float sB[32 * 64];   // [k][f]

  int t  = threadIdx.x;
  int f0 = blockIdx.x * 64;
  int m0 = blockIdx.y * 128;
  int nb = blockIdx.z * KCH;

  int tm = t >> 4, tf = t & 15;      // 16 x 16 thread grid
  int lr = t >> 3, lc = t & 7;       // loader coords: 32 rows, 8 thr/row

  float acc[8][4];
#pragma unroll
  for (int i = 0; i < 8; i++)
#pragma unroll
    for (int j = 0; j < 4; j++) acc[i][j] = 0.0f;

  for (int kk = 0; kk < KCH / 32; kk++) {
    int n0 = nb + kk * 32;
    // load A tile: W[n0+lr][m0 + ...] with mask, layout sA[k][m]
#pragma unroll
    for (int i = 0; i < 4; i++) {
      int c4 = lc + i * 8;  // 0..31 float4s across 128 m
      float4 wv = *reinterpret_cast<const float4*>(
          &W[(size_t)(n0 + lr) * M_CL + m0 + c4 * 4]);
      wv.x = (wv.x >= W_EPS) ? wv.x : 0.0f;
      wv.y = (wv.y >= W_EPS) ? wv.y : 0.0f;
      wv.z = (wv.z >= W_EPS) ? wv.z : 0.0f;
      wv.w = (wv.w >= W_EPS) ? wv.w : 0.0f;
      *reinterpret_cast<float4*>(&sA[lr * 128 + c4 * 4]) = wv;
    }
    // load B tile: P[n0+lr][f0 + ...]
#pragma unroll
    for (int i = 0; i < 2; i++) {
      int c4 = lc + i * 8;  // 0..15 float4s across 64 f
      float4 pv = *reinterpret_cast<const float4*>(
          &g_P[(size_t)(n0 + lr) * FPAD + f0 + c4 * 4]);
      *reinterpret_cast<float4*>(&sB[lr * 64 + c4 * 4]) = pv;
    }
    __syncthreads();
#pragma unroll
    for (int k = 0; k < 32; k++) {
      float4 a0 = *reinterpret_cast<const float4*>(&sA[k * 128 + tm * 8]);
      float4 a1 = *reinterpret_cast<const float4*>(&sA[k * 128 + tm * 8 + 4]);
      float4 b  = *reinterpret_cast<const float4*>(&sB[k * 64 + tf * 4]);
      float am[8] = {a0.x, a0.y, a0.z, a0.w, a1.x, a1.y, a1.z, a1.w};
#pragma unroll
      for (int i = 0; i < 8; i++) {
        acc[i][0] = fmaf(am[i], b.x, acc[i][0]);
        acc[i][1] = fmaf(am[i], b.y, acc[i][1]);
        acc[i][2] = fmaf(am[i], b.z, acc[i][2]);
        acc[i][3] = fmaf(am[i], b.w, acc[i][3]);
      }
    }
    __syncthreads();
  }

  // write partials: part[ks][m][f]
  float* base = g_part + ((size_t)blockIdx.z * M_CL) * FPAD;
#pragma unroll
  for (int i = 0; i < 8; i++) {
    int m = m0 + tm * 8 + i;
    float4 o = make_float4(acc[i][0], acc[i][1], acc[i][2], acc[i][3]);
    *reinterpret_cast<float4*>(&base[(size_t)m * FPAD + f0 + tf * 4]) = o;
  }
}

// ---------------------------------------------------------------------------
// Kernel D: per-m finalize.  Reduce 16 K-split partials into feature vector;
// psi = sum_{k<=l} mult*G_kl*S_kl / Z - ||Omega s||^2 / Z^2,  G = Omega^2.
// ---------------------------------------------------------------------------
__global__ void __launch_bounds__(256) finalize_kernel(const float* __restrict__ Omega,
                                                       float* __restrict__ out) {
  __shared__ float sfeat[NF];
  __shared__ float sO[KD * KD];
  __shared__ float red[256];
  __shared__ float s_trGS, s_cnt;

  int m = blockIdx.x, t = threadIdx.x;

  for (int f = t; f < NF; f += 256) {
    float a = 0.0f;
#pragma unroll
    for (int ks = 0; ks < KSPLIT; ks++)
      a += g_part[((size_t)ks * M_CL + m) * FPAD + f];
    sfeat[f] = a;
  }
  for (int e = t; e < KD * KD; e += 256) sO[e] = Omega[(size_t)m * KD * KD + e];
  if (t < 32) {
    float c = g_cnt[t * M_CL + m];
#pragma unroll
    for (int s = 16; s > 0; s >>= 1) c += __shfl_down_sync(0xffffffffu, c, s);
    if (t == 0) s_cnt = c;
  }
  __syncthreads();

  // tr(G S) over packed triangle (G = Omega * Omega, Omega symmetric)
  float partial = 0.0f;
  for (int ft = t; ft < 528; ft += 256) {
    int k, l;
    tri_decode(ft, k, l);
    float g = 0.0f;
#pragma unroll
    for (int q = 0; q < KD; q++) g = fmaf(sO[k * KD + q], sO[l * KD + q], g);
    float mult = (k == l) ? 1.0f : 2.0f;
    partial = fmaf(mult * g, sfeat[32 + ft], partial);
  }
  red[t] = partial;
  __syncthreads();
  for (int s = 128; s > 0; s >>= 1) { if (t < s) red[t] += red[t + s]; __syncthreads(); }
  if (t == 0) s_trGS = red[0];
  __syncthreads();

  // ||Omega s||^2,  s = sfeat[0..31]
  float up = 0.0f;
  if (t < KD) {
    float u = 0.0f;
#pragma unroll
    for (int q = 0; q < KD; q++) u = fmaf(sO[t * KD + q], sfeat[q], u);
    up = u * u;
  }
  red[t] = up;
  __syncthreads();
  for (int s = 128; s > 0; s >>= 1) { if (t < s) red[t] += red[t + s]; __syncthreads(); }

  if (t == 0) {
    float Z   = fmaxf(sfeat[560], 1e-30f);
    float psi = s_trGS / Z - red[0] / (Z * Z);
    out[m] = (s_cnt >= 1.5f) ? psi : 0.0f;
  }
}

// ---------------------------------------------------------------------------
extern "C" void kernel_launch(void* const* d_in, const int* in_sizes, int n_in,
                              void* d_out, int out_size) {
  const float* W            = (const float*)d_in[0];  // (N, M)
  const float* mu_s         = (const float*)d_in[1];  // (N, K)
  const float* omega_child  = (const float*)d_in[2];  // (N, K, K)
  const float* omega_parent = (const float*)d_in[3];  // (M, K, K)
  float* out = (float*)d_out;                         // (M,)

  solve_kernel<<<N_AG / 8, 256>>>(omega_child, mu_s);
  buildP_kernel<<<N_AG / 8, 256>>>();
  cnt_kernel<<<32, 256>>>(W);
  dim3 gG(FPAD / 64, M_CL / 128, KSPLIT);  // 9 x 2 x 16
  gemm_kernel<<<gG, 256>>>(W);
  finalize_kernel<<<M_CL, 256>>>(omega_parent, out);
}

// round 4
// speedup vs baseline: 3.7607x; 1.0591x over previous
#include <cuda_runtime.h>

#define N_AG 4096
#define M_CL 256
#define KD 32
#define NF 561            /* 32 v + 528 sym-pairs + 1 ones */
#define FPAD 576          /* padded feature stride */
#define KSPLIT 16
#define KCH (N_AG / KSPLIT)   /* 256 */
#define CNT_BLKS 128
#define W_EPS 1e-6f

// static scratch (no allocations allowed)
__device__ float g_P[(size_t)N_AG * FPAD];          // features
__device__ float g_part[(size_t)KSPLIT * M_CL * FPAD];
__device__ float g_cnt[CNT_BLKS * M_CL];

// ---------------------------------------------------------------------------
// Kernel A: batched 32x32 SPD solve (unnormalized Gauss-Jordan, pivot row
// broadcast through shared memory) FUSED with feature build.
// One warp per matrix. Per step: pivot lane stores live q-blocks of its row
// (+b) to smem; all lanes reload as float4 and eliminate. Diagonal captured
// at j==lane (compile-time index). Epilogue writes P[n] = [x, {x_k x_l}, 1, 0s].
// ---------------------------------------------------------------------------
__global__ void __launch_bounds__(256) solve_feat_kernel(const float* __restrict__ A,
                                                         const float* __restrict__ rhs) {
  __shared__ __align__(16) float prow[8][36];
  int t = threadIdx.x, wid = t >> 5, lane = t & 31;
  int n = blockIdx.x * 8 + wid;
  const float* Ar = A + (size_t)n * (KD * KD) + lane * KD;

  float a[KD];
#pragma unroll
  for (int q = 0; q < 8; q++) {
    float4 v4 = *reinterpret_cast<const float4*>(Ar + 4 * q);
    a[4 * q + 0] = v4.x; a[4 * q + 1] = v4.y;
    a[4 * q + 2] = v4.z; a[4 * q + 3] = v4.w;
  }
  float b = rhs[n * KD + lane];
  float diag = 1.0f;
  float* pr = prow[wid];

#pragma unroll
  for (int j = 0; j < KD; j++) {
    if (lane == j) {
#pragma unroll
      for (int q = 0; q < 8; q++)
        if (4 * q + 3 >= j)
          *reinterpret_cast<float4*>(&pr[4 * q]) =
              make_float4(a[4 * q], a[4 * q + 1], a[4 * q + 2], a[4 * q + 3]);
      pr[32] = b;
      diag = a[j];            // exact diagonal for this row (f=0 below)
    }
    __syncwarp();
    float pd  = pr[j];
    float bp  = pr[32];
    float inv = 1.0f / pd;
    float f   = (lane == j) ? 0.0f : a[j] * inv;
#pragma unroll
    for (int q = 0; q < 8; q++)
      if (4 * q + 3 >= j) {
        float4 pv = *reinterpret_cast<const float4*>(&pr[4 * q]);
        a[4 * q + 0] = fmaf(-f, pv.x, a[4 * q + 0]);
        a[4 * q + 1] = fmaf(-f, pv.y, a[4 * q + 1]);
        a[4 * q + 2] = fmaf(-f, pv.z, a[4 * q + 2]);
        a[4 * q + 3] = fmaf(-f, pv.w, a[4 * q + 3]);
      }
    b = fmaf(-f, bp, b);
    __syncwarp();
  }
  float x = b / diag;

  // ---- feature epilogue: stage x through smem, regs; write P row ----
  pr[lane] = x;
  __syncwarp();
  float xv[KD];
#pragma unroll
  for (int q = 0; q < 8; q++) {
    float4 v4 = *reinterpret_cast<const float4*>(&pr[4 * q]);
    xv[4 * q + 0] = v4.x; xv[4 * q + 1] = v4.y;
    xv[4 * q + 2] = v4.z; xv[4 * q + 3] = v4.w;
  }
  float* Pn = g_P + (size_t)n * FPAD;
  Pn[lane] = x;                       // features 0..31 = v
  int base = KD;                      // triangular blocks, constant-folded
#pragma unroll
  for (int k = 0; k < KD; k++) {
    if (lane >= k) Pn[base + lane - k] = xv[k] * x;
    base += KD - k;
  }
  if (lane == 0) Pn[560] = 1.0f;      // ones column (Z)
  if (lane < 15) Pn[561 + lane] = 0.0f;  // pad
}

// ---------------------------------------------------------------------------
// Kernel B: mask count per m, 128 blocks x 32 rows (full SM coverage).
// ---------------------------------------------------------------------------
__global__ void __launch_bounds__(256) cnt_kernel(const float* __restrict__ W) {
  int m = threadIdx.x;
  int nb = blockIdx.x * 32;
  float c = 0.0f;
#pragma unroll 8
  for (int r = 0; r < 32; r++)
    c += (W[(size_t)(nb + r) * M_CL + m] >= W_EPS) ? 1.0f : 0.0f;
  g_cnt[blockIdx.x * M_CL + m] = c;
}

// ---------------------------------------------------------------------------
// Kernel C: GEMM  D[m, f] = sum_n wmask[n, m] * P[n, f].   (at FFMA floor)
// grid (9 f-tiles x 2 m-tiles x 16 k-splits), 256 thr.
// Block tile 128m x 64f, K-chunk 32; thread tile 8m x 4f.
// ---------------------------------------------------------------------------
__global__ void __launch_bounds__(256) gemm_kernel(const float* __restrict__ W) {
  __shared__ __align__(16) float sA[32 * 128];  // [k][m] (masked w)
  __shared__ __align__(16) float sB[32 * 64];   // [k][f]

  int t  = threadIdx.x;
  int f0 = blockIdx.x * 64;
  int m0 = blockIdx.y * 128;
  int nb = blockIdx.z * KCH;

  int tm = t >> 4, tf = t & 15;      // 16 x 16 thread grid
  int lr = t >> 3, lc = t & 7;       // loader coords: 32 rows, 8 thr/row

  float acc[8][4];
#pragma unroll
  for (int i = 0; i < 8; i++)
#pragma unroll
    for (int j = 0; j < 4; j++) acc[i][j] = 0.0f;

  for (int kk = 0; kk < KCH / 32; kk++) {
    int n0 = nb + kk * 32;
#pragma unroll
    for (int i = 0; i < 4; i++) {
      int c4 = lc + i * 8;
      float4 wv = *reinterpret_cast<const float4*>(
          &W[(size_t)(n0 + lr) * M_CL + m0 + c4 * 4]);
      wv.x = (wv.x >= W_EPS) ? wv.x : 0.0f;
      wv.y = (wv.y >= W_EPS) ? wv.y : 0.0f;
      wv.z = (wv.z >= W_EPS) ? wv.z : 0.0f;
      wv.w = (wv.w >= W_EPS) ? wv.w : 0.0f;
      *reinterpret_cast<float4*>(&sA[lr * 128 + c4 * 4]) = wv;
    }
#pragma unroll
    for (int i = 0; i < 2; i++) {
      int c4 = lc + i * 8;
      float4 pv = *reinterpret_cast<const float4*>(
          &g_P[(size_t)(n0 + lr) * FPAD + f0 + c4 * 4]);
      *reinterpret_cast<float4*>(&sB[lr * 64 + c4 * 4]) = pv;
    }
    __syncthreads();
#pragma unroll
    for (int k = 0; k < 32; k++) {
      float4 a0 = *reinterpret_cast<const float4*>(&sA[k * 128 + tm * 8]);
      float4 a1 = *reinterpret_cast<const float4*>(&sA[k * 128 + tm * 8 + 4]);
      float4 bv = *reinterpret_cast<const float4*>(&sB[k * 64 + tf * 4]);
      float am[8] = {a0.x, a0.y, a0.z, a0.w, a1.x, a1.y, a1.z, a1.w};
#pragma unroll
      for (int i = 0; i < 8; i++) {
        acc[i][0] = fmaf(am[i], bv.x, acc[i][0]);
        acc[i][1] = fmaf(am[i], bv.y, acc[i][1]);
        acc[i][2] = fmaf(am[i], bv.z, acc[i][2]);
        acc[i][3] = fmaf(am[i], bv.w, acc[i][3]);
      }
    }
    __syncthreads();
  }

  float* base = g_part + ((size_t)blockIdx.z * M_CL) * FPAD;
#pragma unroll
  for (int i = 0; i < 8; i++) {
    int m = m0 + tm * 8 + i;
    float4 o = make_float4(acc[i][0], acc[i][1], acc[i][2], acc[i][3]);
    *reinterpret_cast<float4*>(&base[(size_t)m * FPAD + f0 + tf * 4]) = o;
  }
}

// ---------------------------------------------------------------------------
// Kernel D: per-m finalize. Reduce K-split partials; G = Omega^2 on the fly
// over the packed triangle; psi = tr(G S)/Z - ||Omega s||^2/Z^2.
// ---------------------------------------------------------------------------
__global__ void __launch_bounds__(256) finalize_kernel(const float* __restrict__ Omega,
                                                       float* __restrict__ out) {
  __shared__ float sfeat[NF];
  __shared__ float sO[KD * KD];
  __shared__ float red[256];
  __shared__ float s_trGS, s_cnt;

  int m = blockIdx.x, t = threadIdx.x;

  for (int f = t; f < NF; f += 256) {
    float a = 0.0f;
#pragma unroll
    for (int ks = 0; ks < KSPLIT; ks++)
      a += g_part[((size_t)ks * M_CL + m) * FPAD + f];
    sfeat[f] = a;
  }
  for (int e = t; e < KD * KD; e += 256) sO[e] = Omega[(size_t)m * KD * KD + e];
  if (t < 32) {
    float c = 0.0f;
#pragma unroll
    for (int i = 0; i < CNT_BLKS / 32; i++) c += g_cnt[(t * (CNT_BLKS / 32) + i) * M_CL + m];
#pragma unroll
    for (int s = 16; s > 0; s >>= 1) c += __shfl_down_sync(0xffffffffu, c, s);
    if (t == 0) s_cnt = c;
  }
  __syncthreads();

  // tr(G S) over packed triangle (G = Omega * Omega, Omega symmetric)
  float partial = 0.0f;
  int ft = t;
  // row starts: feature block k begins at tri(k) = 32k - k(k-1)/2
  for (int k = 0; k < KD; k++) {
    int b0 = k * KD - (k * (k - 1)) / 2;
    int len = KD - k;
    while (ft - b0 < len && ft >= b0) break;  // no-op guard (ft mapping below)
    break;
  }
  // simpler: strided loop with arithmetic decode (no data-dependent loops)
  partial = 0.0f;
  for (ft = t; ft < 528; ft += 256) {
    // decode k from ft: k = floor((65 - sqrt(65^2 - 8 ft)) / 2), exact for ints
    float disc = 4225.0f - 8.0f * (float)ft;
    int k = (int)((65.0f - sqrtf(disc)) * 0.5f);
    int b0 = k * KD - (k * (k - 1)) / 2;
    if (ft < b0) { k--; b0 = k * KD - (k * (k - 1)) / 2; }
    else if (ft >= b0 + (KD - k)) { k++; b0 = k * KD - (k * (k - 1)) / 2; }
    int l = k + (ft - b0);
    float g = 0.0f;
#pragma unroll
    for (int q = 0; q < KD; q++) g = fmaf(sO[k * KD + q], sO[l * KD + q], g);
    float mult = (k == l) ? 1.0f : 2.0f;
    partial = fmaf(mult * g, sfeat[32 + ft], partial);
  }
  red[t] = partial;
  __syncthreads();
  for (int s = 128; s > 0; s >>= 1) { if (t < s) red[t] += red[t + s]; __syncthreads(); }
  if (t == 0) s_trGS = red[0];
  __syncthreads();

  float up = 0.0f;
  if (t < KD) {
    float u = 0.0f;
#pragma unroll
    for (int q = 0; q < KD; q++) u = fmaf(sO[t * KD + q], sfeat[q], u);
    up = u * u;
  }
  red[t] = up;
  __syncthreads();
  for (int s = 128; s > 0; s >>= 1) { if (t < s) red[t] += red[t + s]; __syncthreads(); }

  if (t == 0) {
    float Z   = fmaxf(sfeat[560], 1e-30f);
    float psi = s_trGS / Z - red[0] / (Z * Z);
    out[m] = (s_cnt >= 1.5f) ? psi : 0.0f;
  }
}

// ---------------------------------------------------------------------------
extern "C" void kernel_launch(void* const* d_in, const int* in_sizes, int n_in,
                              void* d_out, int out_size) {
  const float* W            = (const float*)d_in[0];  // (N, M)
  const float* mu_s         = (const float*)d_in[1];  // (N, K)
  const float* omega_child  = (const float*)d_in[2];  // (N, K, K)
  const float* omega_parent = (const float*)d_in[3];  // (M, K, K)
  float* out = (float*)d_out;                         // (M,)

  solve_feat_kernel<<<N_AG / 8, 256>>>(omega_child, mu_s);
  cnt_kernel<<<CNT_BLKS, 256>>>(W);
  dim3 gG(FPAD / 64, M_CL / 128, KSPLIT);  // 9 x 2 x 16
  gemm_kernel<<<gG, 256>>>(W);
  finalize_kernel<<<M_CL, 256>>>(omega_parent, out);
}

// round 5
// speedup vs baseline: 4.1371x; 1.1001x over previous
#include <cuda_runtime.h>

#define N_AG 4096
#define M_CL 256
#define KD 32
#define NF 561            /* 32 v + 528 sym-pairs + 1 ones */
#define FPAD 576          /* padded feature stride */
#define KSPLIT 16
#define KCH (N_AG / KSPLIT)   /* 256 */
#define CNT_BLKS 128
#define W_EPS 1e-6f

// static scratch (no allocations allowed)
__device__ float g_P[(size_t)N_AG * FPAD];          // features
__device__ float g_part[(size_t)KSPLIT * M_CL * FPAD];
__device__ float g_S[(size_t)M_CL * FPAD];          // reduced features per m
__device__ float g_gtri[(size_t)M_CL * 528];        // mult * (Omega^2)_{k<=l}
__device__ float g_cnt[CNT_BLKS * M_CL];

// ---------------------------------------------------------------------------
// Kernel A: batched 32x32 SPD solve (unnormalized Gauss-Jordan, pivot row
// broadcast through shared memory) FUSED with feature build.
// ---------------------------------------------------------------------------
__global__ void __launch_bounds__(256) solve_feat_kernel(const float* __restrict__ A,
                                                         const float* __restrict__ rhs) {
  __shared__ __align__(16) float prow[8][36];
  int t = threadIdx.x, wid = t >> 5, lane = t & 31;
  int n = blockIdx.x * 8 + wid;
  const float* Ar = A + (size_t)n * (KD * KD) + lane * KD;

  float a[KD];
#pragma unroll
  for (int q = 0; q < 8; q++) {
    float4 v4 = *reinterpret_cast<const float4*>(Ar + 4 * q);
    a[4 * q + 0] = v4.x; a[4 * q + 1] = v4.y;
    a[4 * q + 2] = v4.z; a[4 * q + 3] = v4.w;
  }
  float b = rhs[n * KD + lane];
  float diag = 1.0f;
  float* pr = prow[wid];

#pragma unroll
  for (int j = 0; j < KD; j++) {
    if (lane == j) {
#pragma unroll
      for (int q = 0; q < 8; q++)
        if (4 * q + 3 >= j)
          *reinterpret_cast<float4*>(&pr[4 * q]) =
              make_float4(a[4 * q], a[4 * q + 1], a[4 * q + 2], a[4 * q + 3]);
      pr[32] = b;
      diag = a[j];
    }
    __syncwarp();
    float pd  = pr[j];
    float bp  = pr[32];
    float inv = 1.0f / pd;
    float f   = (lane == j) ? 0.0f : a[j] * inv;
#pragma unroll
    for (int q = 0; q < 8; q++)
      if (4 * q + 3 >= j) {
        float4 pv = *reinterpret_cast<const float4*>(&pr[4 * q]);
        a[4 * q + 0] = fmaf(-f, pv.x, a[4 * q + 0]);
        a[4 * q + 1] = fmaf(-f, pv.y, a[4 * q + 1]);
        a[4 * q + 2] = fmaf(-f, pv.z, a[4 * q + 2]);
        a[4 * q + 3] = fmaf(-f, pv.w, a[4 * q + 3]);
      }
    b = fmaf(-f, bp, b);
    __syncwarp();
  }
  float x = b / diag;

  // ---- feature epilogue ----
  pr[lane] = x;
  __syncwarp();
  float xv[KD];
#pragma unroll
  for (int q = 0; q < 8; q++) {
    float4 v4 = *reinterpret_cast<const float4*>(&pr[4 * q]);
    xv[4 * q + 0] = v4.x; xv[4 * q + 1] = v4.y;
    xv[4 * q + 2] = v4.z; xv[4 * q + 3] = v4.w;
  }
  float* Pn = g_P + (size_t)n * FPAD;
  Pn[lane] = x;
  int base = KD;
#pragma unroll
  for (int k = 0; k < KD; k++) {
    if (lane >= k) Pn[base + lane - k] = xv[k] * x;
    base += KD - k;
  }
  if (lane == 0) Pn[560] = 1.0f;
  if (lane < 15) Pn[561 + lane] = 0.0f;
}

// ---------------------------------------------------------------------------
// Kernel G: per-m packed triangle of G = Omega^2 with symmetry multiplier.
// ---------------------------------------------------------------------------
__global__ void __launch_bounds__(256) gsq_kernel(const float* __restrict__ Omega) {
  __shared__ float sO[KD * KD];
  int m = blockIdx.x, t = threadIdx.x;
  for (int e = t; e < KD * KD; e += 256) sO[e] = Omega[(size_t)m * KD * KD + e];
  __syncthreads();
  for (int ft = t; ft < 528; ft += 256) {
    float disc = 4225.0f - 8.0f * (float)ft;
    int k = (int)((65.0f - sqrtf(disc)) * 0.5f);
    int b0 = k * KD - (k * (k - 1)) / 2;
    if (ft < b0) { k--; b0 = k * KD - (k * (k - 1)) / 2; }
    else if (ft >= b0 + (KD - k)) { k++; b0 = k * KD - (k * (k - 1)) / 2; }
    int l = k + (ft - b0);
    float g = 0.0f;
#pragma unroll
    for (int q = 0; q < KD; q++) g = fmaf(sO[k * KD + q], sO[l * KD + q], g);
    g_gtri[(size_t)m * 528 + ft] = (k == l) ? g : 2.0f * g;
  }
}

// ---------------------------------------------------------------------------
// Kernel B: mask count per m, 128 blocks x 32 rows.
// ---------------------------------------------------------------------------
__global__ void __launch_bounds__(256) cnt_kernel(const float* __restrict__ W) {
  int m = threadIdx.x;
  int nb = blockIdx.x * 32;
  float c = 0.0f;
#pragma unroll 8
  for (int r = 0; r < 32; r++)
    c += (W[(size_t)(nb + r) * M_CL + m] >= W_EPS) ? 1.0f : 0.0f;
  g_cnt[blockIdx.x * M_CL + m] = c;
}

// ---------------------------------------------------------------------------
// Kernel C: GEMM  D[m, f] = sum_n wmask[n, m] * P[n, f].   (at FFMA floor)
// ---------------------------------------------------------------------------
__global__ void __launch_bounds__(256) gemm_kernel(const float* __restrict__ W) {
  __shared__ __align__(16) float sA[32 * 128];  // [k][m] (masked w)
  __shared__ __align__(16) float sB[32 * 64];   // [k][f]

  int t  = threadIdx.x;
  int f0 = blockIdx.x * 64;
  int m0 = blockIdx.y * 128;
  int nb = blockIdx.z * KCH;

  int tm = t >> 4, tf = t & 15;
  int lr = t >> 3, lc = t & 7;

  float acc[8][4];
#pragma unroll
  for (int i = 0; i < 8; i++)
#pragma unroll
    for (int j = 0; j < 4; j++) acc[i][j] = 0.0f;

  for (int kk = 0; kk < KCH / 32; kk++) {
    int n0 = nb + kk * 32;
#pragma unroll
    for (int i = 0; i < 4; i++) {
      int c4 = lc + i * 8;
      float4 wv = *reinterpret_cast<const float4*>(
          &W[(size_t)(n0 + lr) * M_CL + m0 + c4 * 4]);
      wv.x = (wv.x >= W_EPS) ? wv.x : 0.0f;
      wv.y = (wv.y >= W_EPS) ? wv.y : 0.0f;
      wv.z = (wv.z >= W_EPS) ? wv.z : 0.0f;
      wv.w = (wv.w >= W_EPS) ? wv.w : 0.0f;
      *reinterpret_cast<float4*>(&sA[lr * 128 + c4 * 4]) = wv;
    }
#pragma unroll
    for (int i = 0; i < 2; i++) {
      int c4 = lc + i * 8;
      float4 pv = *reinterpret_cast<const float4*>(
          &g_P[(size_t)(n0 + lr) * FPAD + f0 + c4 * 4]);
      *reinterpret_cast<float4*>(&sB[lr * 64 + c4 * 4]) = pv;
    }
    __syncthreads();
#pragma unroll
    for (int k = 0; k < 32; k++) {
      float4 a0 = *reinterpret_cast<const float4*>(&sA[k * 128 + tm * 8]);
      float4 a1 = *reinterpret_cast<const float4*>(&sA[k * 128 + tm * 8 + 4]);
      float4 bv = *reinterpret_cast<const float4*>(&sB[k * 64 + tf * 4]);
      float am[8] = {a0.x, a0.y, a0.z, a0.w, a1.x, a1.y, a1.z, a1.w};
#pragma unroll
      for (int i = 0; i < 8; i++) {
        acc[i][0] = fmaf(am[i], bv.x, acc[i][0]);
        acc[i][1] = fmaf(am[i], bv.y, acc[i][1]);
        acc[i][2] = fmaf(am[i], bv.z, acc[i][2]);
        acc[i][3] = fmaf(am[i], bv.w, acc[i][3]);
      }
    }
    __syncthreads();
  }

  float* base = g_part + ((size_t)blockIdx.z * M_CL) * FPAD;
#pragma unroll
  for (int i = 0; i < 8; i++) {
    int m = m0 + tm * 8 + i;
    float4 o = make_float4(acc[i][0], acc[i][1], acc[i][2], acc[i][3]);
    *reinterpret_cast<float4*>(&base[(size_t)m * FPAD + f0 + tf * 4]) = o;
  }
}

// ---------------------------------------------------------------------------
// Kernel R: reduce K-split partials.  One thread per (m, f) element.
// ---------------------------------------------------------------------------
__global__ void __launch_bounds__(256) reduce_kernel() {
  int idx = blockIdx.x * 256 + threadIdx.x;          // 0 .. 256*576-1
  float a = 0.0f;
#pragma unroll
  for (int ks = 0; ks < KSPLIT; ks++)
    a += g_part[(size_t)ks * M_CL * FPAD + idx];
  g_S[idx] = a;
}

// ---------------------------------------------------------------------------
// Kernel F: one warp per m.
// psi = dot(gtri, Stri)/Z - ||Omega s||^2 / Z^2;  0 if count < 2.
// ---------------------------------------------------------------------------
__global__ void __launch_bounds__(256) final_kernel(const float* __restrict__ Omega,
                                                    float* __restrict__ out) {
  int t = threadIdx.x, wid = t >> 5, lane = t & 31;
  int m = blockIdx.x * 8 + wid;

  const float* Sm = g_S + (size_t)m * FPAD;
  const float* Gm = g_gtri + (size_t)m * 528;

  float s_l = Sm[lane];                     // s vector, one element per lane
  float Z   = __shfl_sync(0xffffffffu, Sm[560 - (560 & 31) + (lane & 31)], 0);
  // simpler: read Z directly on every lane (broadcast via L2)
  Z = Sm[560];

  // trGS: strided dot over 528 triangle entries
  float tr = 0.0f;
#pragma unroll
  for (int i = 0; i < 17; i++) {
    int ft = lane + i * 32;
    if (ft < 528) tr = fmaf(Gm[ft], Sm[32 + ft], tr);
  }

  // u_lane = (Omega s)_lane
  const float* Om = Omega + (size_t)m * KD * KD + lane * KD;
  float u = 0.0f;
#pragma unroll
  for (int q4 = 0; q4 < 8; q4++) {
    float4 o4 = *reinterpret_cast<const float4*>(Om + 4 * q4);
    u = fmaf(o4.x, __shfl_sync(0xffffffffu, s_l, 4 * q4 + 0), u);
    u = fmaf(o4.y, __shfl_sync(0xffffffffu, s_l, 4 * q4 + 1), u);
    u = fmaf(o4.z, __shfl_sync(0xffffffffu, s_l, 4 * q4 + 2), u);
    u = fmaf(o4.w, __shfl_sync(0xffffffffu, s_l, 4 * q4 + 3), u);
  }
  float usq = u * u;

  // count: 128 partials per m
  float c = 0.0f;
#pragma unroll
  for (int i = 0; i < CNT_BLKS / 32; i++)
    c += g_cnt[(lane * (CNT_BLKS / 32) + i) * M_CL + m];

#pragma unroll
  for (int s = 16; s > 0; s >>= 1) {
    tr  += __shfl_down_sync(0xffffffffu, tr, s);
    usq += __shfl_down_sync(0xffffffffu, usq, s);
    c   += __shfl_down_sync(0xffffffffu, c, s);
  }
  if (lane == 0) {
    float Zs  = fmaxf(Z, 1e-30f);
    float psi = tr / Zs - usq / (Zs * Zs);
    out[m] = (c >= 1.5f) ? psi : 0.0f;
  }
}

// ---------------------------------------------------------------------------
extern "C" void kernel_launch(void* const* d_in, const int* in_sizes, int n_in,
                              void* d_out, int out_size) {
  const float* W            = (const float*)d_in[0];  // (N, M)
  const float* mu_s         = (const float*)d_in[1];  // (N, K)
  const float* omega_child  = (const float*)d_in[2];  // (N, K, K)
  const float* omega_parent = (const float*)d_in[3];  // (M, K, K)
  float* out = (float*)d_out;                         // (M,)

  gsq_kernel<<<M_CL, 256>>>(omega_parent);            // off critical path
  solve_feat_kernel<<<N_AG / 8, 256>>>(omega_child, mu_s);
  cnt_kernel<<<CNT_BLKS, 256>>>(W);
  dim3 gG(FPAD / 64, M_CL / 128, KSPLIT);  // 9 x 2 x 16
  gemm_kernel<<<gG, 256>>>(W);
  reduce_kernel<<<(M_CL * FPAD) / 256, 256>>>();
  final_kernel<<<M_CL / 8, 256>>>(omega_parent, out);
}